// round 14
// baseline (speedup 1.0000x reference)
#include <cuda_runtime.h>
#include <cuda_bf16.h>
#include <math.h>

#define N_COMBOS   64
#define N_STRUCTS  512
#define HID        1024
#define BATCH      2048
#define NITERS     60
#define POW_ITERS  30
#define MAX_NNZ_G  32768

// ---- PDHG-MMA shared layout (bytes) ----
#define SB_W    260          // S row stride in u32 words (520 bf16)
#define STB_W   36           // S^T row stride in u32 words (72 bf16)
#define OFF_SB   0                          // 64*520*2   = 66560
#define OFF_STB  66560                      // 512*72*2   = 73728
#define OFF_XBH  140288                     // 16*520*2   = 16640
#define OFF_XBL  156928                     // 16640
#define OFF_Y1H  173568                     // 16*72*2    = 2304
#define OFF_Y1L  175872                     // 2304
#define OFF_PART 178176                     // 8*16*4     = 512
#define DYN_PDHG 178688

// ---------------- device scratch ----------------
__device__ float g_Z [BATCH * N_STRUCTS];
__device__ float g_tau;

__device__ __nv_bfloat16 g_Xh[BATCH * N_COMBOS];
__device__ __nv_bfloat16 g_Xl[BATCH * N_COMBOS];
__device__ __nv_bfloat16 g_A1h[BATCH * HID];
__device__ __nv_bfloat16 g_A1l[BATCH * HID];
__device__ __nv_bfloat16 g_A2h[BATCH * HID];
__device__ __nv_bfloat16 g_A2l[BATCH * HID];
__device__ __nv_bfloat16 g_W1hT[HID * N_COMBOS];
__device__ __nv_bfloat16 g_W1lT[HID * N_COMBOS];
__device__ __nv_bfloat16 g_W2hT[HID * HID];
__device__ __nv_bfloat16 g_W2lT[HID * HID];
__device__ __nv_bfloat16 g_W3hT[N_STRUCTS * HID];
__device__ __nv_bfloat16 g_W3lT[N_STRUCTS * HID];

__device__ __nv_bfloat16 g_Sb [64 * 520];    // S row-major bf16, padded
__device__ __nv_bfloat16 g_STb[512 * 72];    // S^T row-major bf16, padded

__device__ int            g_row_ptr[N_COMBOS + 1];
__device__ unsigned short g_row_idx[MAX_NNZ_G];
__device__ int            g_col_ptr[N_STRUCTS + 1];
__device__ unsigned char  g_col_idx[MAX_NNZ_G];

// ---------------- split kernels ----------------
__global__ void split_matrix(const float* __restrict__ src,
                             __nv_bfloat16* __restrict__ hi,
                             __nv_bfloat16* __restrict__ lo, int n) {
    int i = blockIdx.x * blockDim.x + threadIdx.x;
    if (i < n) {
        float x = src[i];
        __nv_bfloat16 h = __float2bfloat16(x);
        hi[i] = h;
        lo[i] = __float2bfloat16(x - __bfloat162float(h));
    }
}

__global__ void split_transpose(const float* __restrict__ W,
                                __nv_bfloat16* __restrict__ hiT,
                                __nv_bfloat16* __restrict__ loT, int K, int N) {
    int i = blockIdx.x * blockDim.x + threadIdx.x;
    if (i < K * N) {
        int k = i / N, n = i % N;
        float x = W[i];
        __nv_bfloat16 h = __float2bfloat16(x);
        hiT[n * K + k] = h;
        loT[n * K + k] = __float2bfloat16(x - __bfloat162float(h));
    }
}

__global__ void build_Sbf16(const float* __restrict__ S) {
    int i = blockIdx.x * blockDim.x + threadIdx.x;
    if (i < 64 * 520) {
        int r = i / 520, c = i % 520;
        g_Sb[i] = (c < 512) ? __float2bfloat16(S[r * 512 + c]) : __float2bfloat16(0.f);
    }
    if (i < 512 * 72) {
        int r = i / 72, c = i % 72;
        g_STb[i] = (c < 64) ? __float2bfloat16(S[c * 512 + r]) : __float2bfloat16(0.f);
    }
}

// ---------------- prep: CSR + CSC (for power iteration) ----------------
__global__ __launch_bounds__(512) void prep_kernel(const float* __restrict__ S) {
    __shared__ int cnt[N_STRUCTS];
    int tid = threadIdx.x;

    if (tid < N_COMBOS) {
        int c = 0;
        for (int j = 0; j < N_STRUCTS; j++) if (S[tid * N_STRUCTS + j] != 0.f) c++;
        cnt[tid] = c;
    }
    __syncthreads();
    if (tid == 0) {
        int acc = 0;
        for (int i = 0; i < N_COMBOS; i++) { g_row_ptr[i] = acc; acc += cnt[i]; }
        g_row_ptr[N_COMBOS] = acc;
    }
    __syncthreads();
    if (tid < N_COMBOS) {
        int p = g_row_ptr[tid];
        for (int j = 0; j < N_STRUCTS; j++)
            if (S[tid * N_STRUCTS + j] != 0.f) g_row_idx[p++] = (unsigned short)j;
    }
    __syncthreads();

    {
        int c = 0;
        for (int i = 0; i < N_COMBOS; i++) if (S[i * N_STRUCTS + tid] != 0.f) c++;
        cnt[tid] = c;
    }
    __syncthreads();
    if (tid == 0) {
        int acc = 0;
        for (int j = 0; j < N_STRUCTS; j++) { g_col_ptr[j] = acc; acc += cnt[j]; }
        g_col_ptr[N_STRUCTS] = acc;
    }
    __syncthreads();
    {
        int p = g_col_ptr[tid];
        for (int i = 0; i < N_COMBOS; i++)
            if (S[i * N_STRUCTS + tid] != 0.f) g_col_idx[p++] = (unsigned char)i;
    }
}

// ---------------- power iteration (unchanged) ----------------
__global__ __launch_bounds__(512) void power_kernel() {
    __shared__ float v[N_STRUCTS];
    __shared__ float t[N_COMBOS];
    __shared__ float red[16];
    int tid = threadIdx.x;

    v[tid] = 1.0f / sqrtf((float)N_STRUCTS);
    __syncthreads();

    for (int it = 0; it < POW_ITERS; it++) {
        if (tid < N_COMBOS) {
            float s = 0.f;
            int pe = g_row_ptr[tid + 1];
            for (int p = g_row_ptr[tid]; p < pe; p++) s += v[g_row_idx[p]];
            t[tid] = s;
        }
        __syncthreads();
        float w;
        {
            float s = 0.f;
            int pe = g_col_ptr[tid + 1];
            for (int p = g_col_ptr[tid]; p < pe; p++) s += t[g_col_idx[p]];
            w = s + v[tid];
        }
        float sq = w * w;
        #pragma unroll
        for (int o = 16; o; o >>= 1) sq += __shfl_xor_sync(0xffffffffu, sq, o);
        if ((tid & 31) == 0) red[tid >> 5] = sq;
        __syncthreads();
        float tot = 0.f;
        #pragma unroll
        for (int k = 0; k < 16; k++) tot += red[k];
        v[tid] = w / sqrtf(tot);
        __syncthreads();
    }

    if (tid < N_COMBOS) {
        float s = 0.f;
        int pe = g_row_ptr[tid + 1];
        for (int p = g_row_ptr[tid]; p < pe; p++) s += v[g_row_idx[p]];
        t[tid] = s;
    }
    __syncthreads();
    float w;
    {
        float s = 0.f;
        int pe = g_col_ptr[tid + 1];
        for (int p = g_col_ptr[tid]; p < pe; p++) s += t[g_col_idx[p]];
        w = s + v[tid];
    }
    float dq = v[tid] * w;
    #pragma unroll
    for (int o = 16; o; o >>= 1) dq += __shfl_xor_sync(0xffffffffu, dq, o);
    if ((tid & 31) == 0) red[tid >> 5] = dq;
    __syncthreads();
    if (tid == 0) {
        float tot = 0.f;
        #pragma unroll
        for (int k = 0; k < 16; k++) tot += red[k];
        g_tau = 0.9f / sqrtf(tot);
    }
}

// ---------------- MMA macro ----------------
#define MMA_BF16(c, a, b) asm volatile( \
    "mma.sync.aligned.m16n8k16.row.col.f32.bf16.bf16.f32 " \
    "{%0,%1,%2,%3}, {%4,%5,%6,%7}, {%8,%9}, {%0,%1,%2,%3};" \
    : "+f"(c[0]), "+f"(c[1]), "+f"(c[2]), "+f"(c[3]) \
    : "r"(a[0]), "r"(a[1]), "r"(a[2]), "r"(a[3]), "r"(b[0]), "r"(b[1]))

__device__ __forceinline__ unsigned pack_bf16x2(float v0, float v1) {
    __nv_bfloat162 b2;
    b2.x = __float2bfloat16(v0);
    b2.y = __float2bfloat16(v1);
    return *(unsigned*)&b2;
}
__device__ __forceinline__ unsigned pack_bf16x2_res(float v0, float v1, unsigned hibits) {
    __nv_bfloat162 hb = *(__nv_bfloat162*)&hibits;
    __nv_bfloat162 b2;
    b2.x = __float2bfloat16(v0 - __bfloat162float(hb.x));
    b2.y = __float2bfloat16(v1 - __bfloat162float(hb.y));
    return *(unsigned*)&b2;
}

// ---------------- bf16-split tensor-core GEMM (double-buffered) ----------------
__global__ __launch_bounds__(256) void gemm_bf16split(
    const __nv_bfloat16* __restrict__ Ah, const __nv_bfloat16* __restrict__ Al,
    const __nv_bfloat16* __restrict__ BhT, const __nv_bfloat16* __restrict__ BlT,
    const float* __restrict__ bias,
    float* __restrict__ C,
    __nv_bfloat16* __restrict__ Ch, __nv_bfloat16* __restrict__ Cl,
    int N, int K)
{
    __shared__ __align__(16) unsigned As[2][2][128 * 9];   // [stage][prec]
    __shared__ __align__(16) unsigned Bs[2][2][64 * 9];

    const int tid  = threadIdx.x;
    const int bm   = blockIdx.y * 128;
    const int bn   = blockIdx.x * 64;
    const int wid  = tid >> 5, lane = tid & 31;
    const int wm   = (wid & 3) * 32;
    const int wn   = (wid >> 2) * 32;
    const int g    = lane >> 2;
    const int t4   = lane & 3;

    // load-tile index precomputes
    const int a_h    = tid & 1;
    const int a_row  = (tid >> 1) & 127;
    const int a_prec = tid >> 8;          // rep adds +1
    const int b_h    = tid & 1;
    const int b_row  = (tid >> 1) & 63;
    const int b_prec = tid >> 7;

    float acc[2][4][4];
    #pragma unroll
    for (int mt = 0; mt < 2; mt++)
        #pragma unroll
        for (int nt = 0; nt < 4; nt++)
            #pragma unroll
            for (int c = 0; c < 4; c++) acc[mt][nt][c] = 0.f;

    const int ksteps = K >> 4;

    // prologue: load tile 0 into stage 0
    {
        const int k0 = 0;
        #pragma unroll
        for (int rep = 0; rep < 2; rep++) {
            int prec = a_prec + rep;  // rep0: 0 or 1; tid<256 so a_prec=0; rep1 -> 1
            const __nv_bfloat16* Ap = prec ? Al : Ah;
            uint4 v = *(const uint4*)&Ap[(size_t)(bm + a_row) * K + k0 + a_h * 8];
            unsigned* dst = &As[0][prec][a_row * 9 + a_h * 4];
            dst[0] = v.x; dst[1] = v.y; dst[2] = v.z; dst[3] = v.w;
        }
        {
            const __nv_bfloat16* Bp = b_prec ? BlT : BhT;
            uint4 v = *(const uint4*)&Bp[(size_t)(bn + b_row) * K + k0 + b_h * 8];
            unsigned* dst = &Bs[0][b_prec][b_row * 9 + b_h * 4];
            dst[0] = v.x; dst[1] = v.y; dst[2] = v.z; dst[3] = v.w;
        }
    }
    __syncthreads();

    for (int ks = 0; ks < ksteps; ks++) {
        const int s = ks & 1;
        // prefetch next tile into other stage (no sync needed: that stage is idle)
        if (ks + 1 < ksteps) {
            const int k0 = (ks + 1) << 4;
            const int sn = s ^ 1;
            #pragma unroll
            for (int rep = 0; rep < 2; rep++) {
                int prec = a_prec + rep;
                const __nv_bfloat16* Ap = prec ? Al : Ah;
                uint4 v = *(const uint4*)&Ap[(size_t)(bm + a_row) * K + k0 + a_h * 8];
                unsigned* dst = &As[sn][prec][a_row * 9 + a_h * 4];
                dst[0] = v.x; dst[1] = v.y; dst[2] = v.z; dst[3] = v.w;
            }
            {
                const __nv_bfloat16* Bp = b_prec ? BlT : BhT;
                uint4 v = *(const uint4*)&Bp[(size_t)(bn + b_row) * K + k0 + b_h * 8];
                unsigned* dst = &Bs[sn][b_prec][b_row * 9 + b_h * 4];
                dst[0] = v.x; dst[1] = v.y; dst[2] = v.z; dst[3] = v.w;
            }
        }

        unsigned afh[2][4], afl[2][4], bfh[4][2], bfl[4][2];
        #pragma unroll
        for (int mt = 0; mt < 2; mt++) {
            int mb = wm + mt * 16;
            afh[mt][0] = As[s][0][(mb + g) * 9 + t4];
            afh[mt][1] = As[s][0][(mb + g + 8) * 9 + t4];
            afh[mt][2] = As[s][0][(mb + g) * 9 + 4 + t4];
            afh[mt][3] = As[s][0][(mb + g + 8) * 9 + 4 + t4];
            afl[mt][0] = As[s][1][(mb + g) * 9 + t4];
            afl[mt][1] = As[s][1][(mb + g + 8) * 9 + t4];
            afl[mt][2] = As[s][1][(mb + g) * 9 + 4 + t4];
            afl[mt][3] = As[s][1][(mb + g + 8) * 9 + 4 + t4];
        }
        #pragma unroll
        for (int nt = 0; nt < 4; nt++) {
            int nb = wn + nt * 8;
            bfh[nt][0] = Bs[s][0][(nb + g) * 9 + t4];
            bfh[nt][1] = Bs[s][0][(nb + g) * 9 + 4 + t4];
            bfl[nt][0] = Bs[s][1][(nb + g) * 9 + t4];
            bfl[nt][1] = Bs[s][1][(nb + g) * 9 + 4 + t4];
        }
        #pragma unroll
        for (int mt = 0; mt < 2; mt++)
            #pragma unroll
            for (int nt = 0; nt < 4; nt++) {
                MMA_BF16(acc[mt][nt], afh[mt], bfh[nt]);
                MMA_BF16(acc[mt][nt], afh[mt], bfl[nt]);
                MMA_BF16(acc[mt][nt], afl[mt], bfh[nt]);
            }
        __syncthreads();
    }

    #pragma unroll
    for (int mt = 0; mt < 2; mt++) {
        #pragma unroll
        for (int nt = 0; nt < 4; nt++) {
            int row0 = bm + wm + mt * 16 + g;
            int col  = bn + wn + nt * 8 + t4 * 2;
            float b0 = bias[col], b1 = bias[col + 1];
            float r00 = acc[mt][nt][0] + b0; r00 = r00 > 0.f ? r00 : 0.f;
            float r01 = acc[mt][nt][1] + b1; r01 = r01 > 0.f ? r01 : 0.f;
            float r10 = acc[mt][nt][2] + b0; r10 = r10 > 0.f ? r10 : 0.f;
            float r11 = acc[mt][nt][3] + b1; r11 = r11 > 0.f ? r11 : 0.f;
            if (C) {
                *(float2*)&C[(size_t)row0 * N + col]       = make_float2(r00, r01);
                *(float2*)&C[(size_t)(row0 + 8) * N + col] = make_float2(r10, r11);
            }
            if (Ch) {
                unsigned h0 = pack_bf16x2(r00, r01);
                unsigned h1 = pack_bf16x2(r10, r11);
                *(unsigned*)&Ch[(size_t)row0 * N + col]       = h0;
                *(unsigned*)&Ch[(size_t)(row0 + 8) * N + col] = h1;
                *(unsigned*)&Cl[(size_t)row0 * N + col]       = pack_bf16x2_res(r00, r01, h0);
                *(unsigned*)&Cl[(size_t)(row0 + 8) * N + col] = pack_bf16x2_res(r10, r11, h1);
            }
        }
    }
}

// ---------------- PDHG via dense MMA (R12 + 4-way dir1 chain split) ----------------
__global__ __launch_bounds__(256, 1) void pdhg_mma_kernel(
    const float* __restrict__ Zg, const float* __restrict__ Xg,
    float* __restrict__ out)
{
    extern __shared__ __align__(16) char dyn[];
    unsigned* Sb_u  = (unsigned*)(dyn + OFF_SB);    // [64][260]
    unsigned* STb_u = (unsigned*)(dyn + OFF_STB);   // [512][36]
    unsigned* xbh_u = (unsigned*)(dyn + OFF_XBH);   // [16][260]
    unsigned* xbl_u = (unsigned*)(dyn + OFF_XBL);
    unsigned* y1h_u = (unsigned*)(dyn + OFF_Y1H);   // [16][36]
    unsigned* y1l_u = (unsigned*)(dyn + OFF_Y1L);
    float*    part  = (float*)(dyn + OFF_PART);     // [8][16]

    const int tid = threadIdx.x;
    const int w = tid >> 5, lane = tid & 31;
    const int g = lane >> 2, t4 = lane & 3;
    const int row0 = blockIdx.x * 16;
    const float tau = g_tau, sigma = tau;

    {
        const uint4* src = (const uint4*)g_Sb;
        uint4* dst = (uint4*)Sb_u;
        for (int p = tid; p < (64 * 520 * 2) / 16; p += 256) dst[p] = src[p];
        const uint4* src2 = (const uint4*)g_STb;
        uint4* dst2 = (uint4*)STb_u;
        for (int p = tid; p < (512 * 72 * 2) / 16; p += 256) dst2[p] = src2[p];
    }
    for (int p = tid; p < 16 * 260; p += 256) { xbh_u[p] = 0u; xbl_u[p] = 0u; }

    float x[32], y2[32], Zr[32];
    #pragma unroll
    for (int tt = 0; tt < 8; tt++) {
        int col = w * 8 + tt * 64 + 2 * t4;
        float2 z0 = *(const float2*)&Zg[(size_t)(row0 + g) * N_STRUCTS + col];
        float2 z1 = *(const float2*)&Zg[(size_t)(row0 + g + 8) * N_STRUCTS + col];
        Zr[tt * 4 + 0] = z0.x; Zr[tt * 4 + 1] = z0.y;
        Zr[tt * 4 + 2] = z1.x; Zr[tt * 4 + 3] = z1.y;
        #pragma unroll
        for (int e = 0; e < 4; e++) { x[tt * 4 + e] = 0.f; y2[tt * 4 + e] = 0.f; }
    }
    float y1v[4] = {0.f, 0.f, 0.f, 0.f};
    float Bc[4];
    Bc[0] = Xg[(row0 + g) * N_COMBOS + w * 8 + 2 * t4];
    Bc[1] = Xg[(row0 + g) * N_COMBOS + w * 8 + 2 * t4 + 1];
    Bc[2] = Xg[(row0 + g + 8) * N_COMBOS + w * 8 + 2 * t4];
    Bc[3] = Xg[(row0 + g + 8) * N_COMBOS + w * 8 + 2 * t4 + 1];
    __syncthreads();

    for (int it = 0; it < NITERS; it++) {
        // ---- dir1: t = xbar @ S^T ; 4 independent accumulator chains ----
        float c1[4][4];
        #pragma unroll
        for (int ch = 0; ch < 4; ch++)
            #pragma unroll
            for (int e = 0; e < 4; e++) c1[ch][e] = 0.f;
        #pragma unroll 4
        for (int ks = 0; ks < 32; ks++) {
            int kw = ks * 8;
            int a0 = g * SB_W + kw + t4, a1 = (g + 8) * SB_W + kw + t4;
            unsigned ah[4], al[4], bs[2];
            ah[0] = xbh_u[a0]; ah[1] = xbh_u[a1]; ah[2] = xbh_u[a0 + 4]; ah[3] = xbh_u[a1 + 4];
            al[0] = xbl_u[a0]; al[1] = xbl_u[a1]; al[2] = xbl_u[a0 + 4]; al[3] = xbl_u[a1 + 4];
            int br = (w * 8 + g) * SB_W + kw + t4;
            bs[0] = Sb_u[br]; bs[1] = Sb_u[br + 4];
            MMA_BF16(c1[(ks & 1) * 2],     ah, bs);
            MMA_BF16(c1[(ks & 1) * 2 + 1], al, bs);
        }
        // y1 update, write hi/lo to shared
        #pragma unroll
        for (int e = 0; e < 4; e++) {
            float t1 = (c1[0][e] + c1[1][e]) + (c1[2][e] + c1[3][e]);
            y1v[e] = fmaxf(fmaf(sigma, t1 - Bc[e], y1v[e]), 0.f);
        }
        {
            int w0 = g * STB_W + w * 4 + t4;
            int w1 = (g + 8) * STB_W + w * 4 + t4;
            unsigned h0 = pack_bf16x2(y1v[0], y1v[1]);
            unsigned h1 = pack_bf16x2(y1v[2], y1v[3]);
            y1h_u[w0] = h0;
            y1h_u[w1] = h1;
            y1l_u[w0] = pack_bf16x2_res(y1v[0], y1v[1], h0);
            y1l_u[w1] = pack_bf16x2_res(y1v[2], y1v[3], h1);
        }
        __syncthreads();

        // ---- dir2: g = y1 @ S ; 8 independent tt chains ----
        float c2a[8][4];
        #pragma unroll
        for (int tt = 0; tt < 8; tt++)
            #pragma unroll
            for (int e = 0; e < 4; e++) c2a[tt][e] = 0.f;
        #pragma unroll
        for (int ks = 0; ks < 4; ks++) {
            int kw = ks * 8;
            int a0 = g * STB_W + kw + t4, a1 = (g + 8) * STB_W + kw + t4;
            unsigned ah[4], al[4];
            ah[0] = y1h_u[a0]; ah[1] = y1h_u[a1]; ah[2] = y1h_u[a0 + 4]; ah[3] = y1h_u[a1 + 4];
            al[0] = y1l_u[a0]; al[1] = y1l_u[a1]; al[2] = y1l_u[a0 + 4]; al[3] = y1l_u[a1 + 4];
            #pragma unroll
            for (int tt = 0; tt < 8; tt++) {
                int br = (w * 8 + tt * 64 + g) * STB_W + kw + t4;
                unsigned bs[2] = { STb_u[br], STb_u[br + 4] };
                MMA_BF16(c2a[tt], ah, bs);
                MMA_BF16(c2a[tt], al, bs);
            }
        }

        // ---- elementwise: d, per-batch sumsq ----
        float sq0 = 0.f, sq1 = 0.f;
        #pragma unroll
        for (int tt = 0; tt < 8; tt++) {
            #pragma unroll
            for (int e = 0; e < 4; e++) {
                int idx = tt * 4 + e;
                float gv = c2a[tt][e] - y2[idx];
                float v  = fmaf(-tau, gv, x[idx]);
                float d  = v + tau - Zr[idx];
                c2a[tt][e] = d;
                if (e < 2) sq0 = fmaf(d, d, sq0); else sq1 = fmaf(d, d, sq1);
            }
        }
        sq0 += __shfl_xor_sync(0xffffffffu, sq0, 1);
        sq0 += __shfl_xor_sync(0xffffffffu, sq0, 2);
        sq1 += __shfl_xor_sync(0xffffffffu, sq1, 1);
        sq1 += __shfl_xor_sync(0xffffffffu, sq1, 2);
        if (t4 == 0) { part[w * 16 + g] = sq0; part[w * 16 + g + 8] = sq1; }
        __syncthreads();

        float tot0 = 0.f, tot1 = 0.f;
        #pragma unroll
        for (int ww = 0; ww < 8; ww++) {
            tot0 += part[ww * 16 + g];
            tot1 += part[ww * 16 + g + 8];
        }
        float sc0 = fmaxf(1.f - tau / fmaxf(sqrtf(tot0), 1e-12f), 0.f);
        float sc1 = fmaxf(1.f - tau / fmaxf(sqrtf(tot1), 1e-12f), 0.f);

        // ---- prox, xbar, pre-applied y2 update, store xbar hi/lo ----
        #pragma unroll
        for (int tt = 0; tt < 8; tt++) {
            float xb0, xb1, xb2, xb3;
            {
                int i0 = tt * 4 + 0, i1 = tt * 4 + 1;
                float xn0 = fmaf(sc0, c2a[tt][0], Zr[i0]);
                float xn1 = fmaf(sc0, c2a[tt][1], Zr[i1]);
                xb0 = 2.f * xn0 - x[i0]; xb1 = 2.f * xn1 - x[i1];
                x[i0] = xn0; x[i1] = xn1;
                y2[i0] = fmaxf(fmaf(-sigma, xb0, y2[i0]), 0.f);
                y2[i1] = fmaxf(fmaf(-sigma, xb1, y2[i1]), 0.f);
            }
            {
                int i2 = tt * 4 + 2, i3 = tt * 4 + 3;
                float xn2 = fmaf(sc1, c2a[tt][2], Zr[i2]);
                float xn3 = fmaf(sc1, c2a[tt][3], Zr[i3]);
                xb2 = 2.f * xn2 - x[i2]; xb3 = 2.f * xn3 - x[i3];
                x[i2] = xn2; x[i3] = xn3;
                y2[i2] = fmaxf(fmaf(-sigma, xb2, y2[i2]), 0.f);
                y2[i3] = fmaxf(fmaf(-sigma, xb3, y2[i3]), 0.f);
            }
            int w0 = g * SB_W + tt * 32 + w * 4 + t4;
            int w1 = (g + 8) * SB_W + tt * 32 + w * 4 + t4;
            unsigned h0 = pack_bf16x2(xb0, xb1);
            unsigned h1 = pack_bf16x2(xb2, xb3);
            xbh_u[w0] = h0;
            xbh_u[w1] = h1;
            xbl_u[w0] = pack_bf16x2_res(xb0, xb1, h0);
            xbl_u[w1] = pack_bf16x2_res(xb2, xb3, h1);
        }
        __syncthreads();
    }

    #pragma unroll
    for (int tt = 0; tt < 8; tt++) {
        int col = w * 8 + tt * 64 + 2 * t4;
        *(float2*)&out[(size_t)(row0 + g) * N_STRUCTS + col] =
            make_float2(x[tt * 4 + 0], x[tt * 4 + 1]);
        *(float2*)&out[(size_t)(row0 + g + 8) * N_STRUCTS + col] =
            make_float2(x[tt * 4 + 2], x[tt * 4 + 3]);
    }
}

// ---------------- launch ----------------
extern "C" void kernel_launch(void* const* d_in, const int* in_sizes, int n_in,
                              void* d_out, int out_size) {
    const float* X  = (const float*)d_in[0];
    const float* W1 = (const float*)d_in[1];
    const float* b1 = (const float*)d_in[2];
    const float* W2 = (const float*)d_in[3];
    const float* b2 = (const float*)d_in[4];
    const float* W3 = (const float*)d_in[5];
    const float* b3 = (const float*)d_in[6];
    const float* S  = (const float*)d_in[7];
    float* out = (float*)d_out;

    float *Z;
    __nv_bfloat16 *Xh, *Xl, *A1h, *A1l, *A2h, *A2l;
    __nv_bfloat16 *W1hT, *W1lT, *W2hT, *W2lT, *W3hT, *W3lT;
    cudaGetSymbolAddress((void**)&Z,    g_Z);
    cudaGetSymbolAddress((void**)&Xh,   g_Xh);
    cudaGetSymbolAddress((void**)&Xl,   g_Xl);
    cudaGetSymbolAddress((void**)&A1h,  g_A1h);
    cudaGetSymbolAddress((void**)&A1l,  g_A1l);
    cudaGetSymbolAddress((void**)&A2h,  g_A2h);
    cudaGetSymbolAddress((void**)&A2l,  g_A2l);
    cudaGetSymbolAddress((void**)&W1hT, g_W1hT);
    cudaGetSymbolAddress((void**)&W1lT, g_W1lT);
    cudaGetSymbolAddress((void**)&W2hT, g_W2hT);
    cudaGetSymbolAddress((void**)&W2lT, g_W2lT);
    cudaGetSymbolAddress((void**)&W3hT, g_W3hT);
    cudaGetSymbolAddress((void**)&W3lT, g_W3lT);

    static int smem_set = 0;
    if (!smem_set) {
        cudaFuncSetAttribute(pdhg_mma_kernel,
                             cudaFuncAttributeMaxDynamicSharedMemorySize, DYN_PDHG);
        smem_set = 1;
    }

    prep_kernel<<<1, 512>>>(S);
    power_kernel<<<1, 512>>>();
    build_Sbf16<<<(512 * 72 + 511) / 512, 512>>>(S);

    split_matrix<<<(BATCH * N_COMBOS + 255) / 256, 256>>>(X, Xh, Xl, BATCH * N_COMBOS);
    split_transpose<<<(N_COMBOS * HID + 255) / 256, 256>>>(W1, W1hT, W1lT, N_COMBOS, HID);
    split_transpose<<<(HID * HID + 255) / 256, 256>>>(W2, W2hT, W2lT, HID, HID);
    split_transpose<<<(HID * N_STRUCTS + 255) / 256, 256>>>(W3, W3hT, W3lT, HID, N_STRUCTS);

    gemm_bf16split<<<dim3(HID / 64, BATCH / 128), 256>>>(
        Xh, Xl, W1hT, W1lT, b1, nullptr, A1h, A1l, HID, N_COMBOS);
    gemm_bf16split<<<dim3(HID / 64, BATCH / 128), 256>>>(
        A1h, A1l, W2hT, W2lT, b2, nullptr, A2h, A2l, HID, HID);
    gemm_bf16split<<<dim3(N_STRUCTS / 64, BATCH / 128), 256>>>(
        A2h, A2l, W3hT, W3lT, b3, Z, nullptr, nullptr, N_STRUCTS, HID);

    pdhg_mma_kernel<<<BATCH / 16, 256, DYN_PDHG>>>(Z, X, out);
}

// round 15
// speedup vs baseline: 1.5406x; 1.5406x over previous
#include <cuda_runtime.h>
#include <cuda_bf16.h>
#include <math.h>

#define N_COMBOS   64
#define N_STRUCTS  512
#define HID        1024
#define BATCH      2048
#define NITERS     60
#define POW_ITERS  30
#define MAX_NNZ_G  32768

// ---- PDHG-MMA shared layout (bytes) ----
#define SB_W    260          // S row stride in u32 words (520 bf16)
#define STB_W   36           // S^T row stride in u32 words (72 bf16)
#define OFF_SB   0                          // 64*520*2   = 66560
#define OFF_STB  66560                      // 512*72*2   = 73728
#define OFF_XBH  140288                     // 16*520*2   = 16640
#define OFF_XBL  156928                     // 16640
#define OFF_Y1H  173568                     // 16*72*2    = 2304
#define OFF_Y1L  175872                     // 2304
#define OFF_PART 178176                     // 8*16*4     = 512
#define DYN_PDHG 178688

// ---------------- device scratch ----------------
__device__ float g_Z [BATCH * N_STRUCTS];
__device__ float g_tau;

__device__ __nv_bfloat16 g_Xh[BATCH * N_COMBOS];
__device__ __nv_bfloat16 g_Xl[BATCH * N_COMBOS];
__device__ __nv_bfloat16 g_A1h[BATCH * HID];
__device__ __nv_bfloat16 g_A1l[BATCH * HID];
__device__ __nv_bfloat16 g_A2h[BATCH * HID];
__device__ __nv_bfloat16 g_A2l[BATCH * HID];
__device__ __nv_bfloat16 g_W1hT[HID * N_COMBOS];
__device__ __nv_bfloat16 g_W1lT[HID * N_COMBOS];
__device__ __nv_bfloat16 g_W2hT[HID * HID];
__device__ __nv_bfloat16 g_W2lT[HID * HID];
__device__ __nv_bfloat16 g_W3hT[N_STRUCTS * HID];
__device__ __nv_bfloat16 g_W3lT[N_STRUCTS * HID];

__device__ __nv_bfloat16 g_Sb [64 * 520];    // S row-major bf16, padded
__device__ __nv_bfloat16 g_STb[512 * 72];    // S^T row-major bf16, padded

__device__ int            g_row_ptr[N_COMBOS + 1];
__device__ unsigned short g_row_idx[MAX_NNZ_G];
__device__ int            g_col_ptr[N_STRUCTS + 1];
__device__ unsigned char  g_col_idx[MAX_NNZ_G];

// ---------------- split kernels ----------------
__global__ void split_matrix(const float* __restrict__ src,
                             __nv_bfloat16* __restrict__ hi,
                             __nv_bfloat16* __restrict__ lo, int n) {
    int i = blockIdx.x * blockDim.x + threadIdx.x;
    if (i < n) {
        float x = src[i];
        __nv_bfloat16 h = __float2bfloat16(x);
        hi[i] = h;
        lo[i] = __float2bfloat16(x - __bfloat162float(h));
    }
}

__global__ void split_transpose(const float* __restrict__ W,
                                __nv_bfloat16* __restrict__ hiT,
                                __nv_bfloat16* __restrict__ loT, int K, int N) {
    int i = blockIdx.x * blockDim.x + threadIdx.x;
    if (i < K * N) {
        int k = i / N, n = i % N;
        float x = W[i];
        __nv_bfloat16 h = __float2bfloat16(x);
        hiT[n * K + k] = h;
        loT[n * K + k] = __float2bfloat16(x - __bfloat162float(h));
    }
}

__global__ void build_Sbf16(const float* __restrict__ S) {
    int i = blockIdx.x * blockDim.x + threadIdx.x;
    if (i < 64 * 520) {
        int r = i / 520, c = i % 520;
        g_Sb[i] = (c < 512) ? __float2bfloat16(S[r * 512 + c]) : __float2bfloat16(0.f);
    }
    if (i < 512 * 72) {
        int r = i / 72, c = i % 72;
        g_STb[i] = (c < 64) ? __float2bfloat16(S[c * 512 + r]) : __float2bfloat16(0.f);
    }
}

// ---------------- prep: CSR + CSC (for power iteration) ----------------
__global__ __launch_bounds__(512) void prep_kernel(const float* __restrict__ S) {
    __shared__ int cnt[N_STRUCTS];
    int tid = threadIdx.x;

    if (tid < N_COMBOS) {
        int c = 0;
        for (int j = 0; j < N_STRUCTS; j++) if (S[tid * N_STRUCTS + j] != 0.f) c++;
        cnt[tid] = c;
    }
    __syncthreads();
    if (tid == 0) {
        int acc = 0;
        for (int i = 0; i < N_COMBOS; i++) { g_row_ptr[i] = acc; acc += cnt[i]; }
        g_row_ptr[N_COMBOS] = acc;
    }
    __syncthreads();
    if (tid < N_COMBOS) {
        int p = g_row_ptr[tid];
        for (int j = 0; j < N_STRUCTS; j++)
            if (S[tid * N_STRUCTS + j] != 0.f) g_row_idx[p++] = (unsigned short)j;
    }
    __syncthreads();

    {
        int c = 0;
        for (int i = 0; i < N_COMBOS; i++) if (S[i * N_STRUCTS + tid] != 0.f) c++;
        cnt[tid] = c;
    }
    __syncthreads();
    if (tid == 0) {
        int acc = 0;
        for (int j = 0; j < N_STRUCTS; j++) { g_col_ptr[j] = acc; acc += cnt[j]; }
        g_col_ptr[N_STRUCTS] = acc;
    }
    __syncthreads();
    {
        int p = g_col_ptr[tid];
        for (int i = 0; i < N_COMBOS; i++)
            if (S[i * N_STRUCTS + tid] != 0.f) g_col_idx[p++] = (unsigned char)i;
    }
}

// ---------------- power iteration ----------------
__global__ __launch_bounds__(512) void power_kernel() {
    __shared__ float v[N_STRUCTS];
    __shared__ float t[N_COMBOS];
    __shared__ float red[16];
    int tid = threadIdx.x;

    v[tid] = 1.0f / sqrtf((float)N_STRUCTS);
    __syncthreads();

    for (int it = 0; it < POW_ITERS; it++) {
        if (tid < N_COMBOS) {
            float s = 0.f;
            int pe = g_row_ptr[tid + 1];
            for (int p = g_row_ptr[tid]; p < pe; p++) s += v[g_row_idx[p]];
            t[tid] = s;
        }
        __syncthreads();
        float w;
        {
            float s = 0.f;
            int pe = g_col_ptr[tid + 1];
            for (int p = g_col_ptr[tid]; p < pe; p++) s += t[g_col_idx[p]];
            w = s + v[tid];
        }
        float sq = w * w;
        #pragma unroll
        for (int o = 16; o; o >>= 1) sq += __shfl_xor_sync(0xffffffffu, sq, o);
        if ((tid & 31) == 0) red[tid >> 5] = sq;
        __syncthreads();
        float tot = 0.f;
        #pragma unroll
        for (int k = 0; k < 16; k++) tot += red[k];
        v[tid] = w / sqrtf(tot);
        __syncthreads();
    }

    if (tid < N_COMBOS) {
        float s = 0.f;
        int pe = g_row_ptr[tid + 1];
        for (int p = g_row_ptr[tid]; p < pe; p++) s += v[g_row_idx[p]];
        t[tid] = s;
    }
    __syncthreads();
    float w;
    {
        float s = 0.f;
        int pe = g_col_ptr[tid + 1];
        for (int p = g_col_ptr[tid]; p < pe; p++) s += t[g_col_idx[p]];
        w = s + v[tid];
    }
    float dq = v[tid] * w;
    #pragma unroll
    for (int o = 16; o; o >>= 1) dq += __shfl_xor_sync(0xffffffffu, dq, o);
    if ((tid & 31) == 0) red[tid >> 5] = dq;
    __syncthreads();
    if (tid == 0) {
        float tot = 0.f;
        #pragma unroll
        for (int k = 0; k < 16; k++) tot += red[k];
        g_tau = 0.9f / sqrtf(tot);
    }
}

// ---------------- MMA macro ----------------
#define MMA_BF16(c, a, b) asm volatile( \
    "mma.sync.aligned.m16n8k16.row.col.f32.bf16.bf16.f32 " \
    "{%0,%1,%2,%3}, {%4,%5,%6,%7}, {%8,%9}, {%0,%1,%2,%3};" \
    : "+f"(c[0]), "+f"(c[1]), "+f"(c[2]), "+f"(c[3]) \
    : "r"(a[0]), "r"(a[1]), "r"(a[2]), "r"(a[3]), "r"(b[0]), "r"(b[1]))

__device__ __forceinline__ unsigned pack_bf16x2(float v0, float v1) {
    __nv_bfloat162 b2;
    b2.x = __float2bfloat16(v0);
    b2.y = __float2bfloat16(v1);
    return *(unsigned*)&b2;
}
__device__ __forceinline__ unsigned pack_bf16x2_res(float v0, float v1, unsigned hibits) {
    __nv_bfloat162 hb = *(__nv_bfloat162*)&hibits;
    __nv_bfloat162 b2;
    b2.x = __float2bfloat16(v0 - __bfloat162float(hb.x));
    b2.y = __float2bfloat16(v1 - __bfloat162float(hb.y));
    return *(unsigned*)&b2;
}

// ---------------- bf16-split tensor-core GEMM (R11/R12 verbatim) ----------------
__global__ __launch_bounds__(256) void gemm_bf16split(
    const __nv_bfloat16* __restrict__ Ah, const __nv_bfloat16* __restrict__ Al,
    const __nv_bfloat16* __restrict__ BhT, const __nv_bfloat16* __restrict__ BlT,
    const float* __restrict__ bias,
    float* __restrict__ C,
    __nv_bfloat16* __restrict__ Ch, __nv_bfloat16* __restrict__ Cl,
    int N, int K)
{
    __shared__ __align__(16) unsigned As[2][128 * 9];
    __shared__ __align__(16) unsigned Bs[2][64 * 9];

    const int tid  = threadIdx.x;
    const int bm   = blockIdx.y * 128;
    const int bn   = blockIdx.x * 64;
    const int wid  = tid >> 5, lane = tid & 31;
    const int wm   = (wid & 3) * 32;
    const int wn   = (wid >> 2) * 32;
    const int g    = lane >> 2;
    const int t4   = lane & 3;

    float acc[2][4][4];
    #pragma unroll
    for (int mt = 0; mt < 2; mt++)
        #pragma unroll
        for (int nt = 0; nt < 4; nt++)
            #pragma unroll
            for (int c = 0; c < 4; c++) acc[mt][nt][c] = 0.f;

    const int ksteps = K >> 4;
    for (int ks = 0; ks < ksteps; ks++) {
        const int k0 = ks << 4;
        #pragma unroll
        for (int rep = 0; rep < 2; rep++) {
            int it = tid + rep * 256;
            int h = it & 1;
            int row = (it >> 1) & 127;
            int prec = it >> 8;
            const __nv_bfloat16* Ap = prec ? Al : Ah;
            uint4 v = *(const uint4*)&Ap[(size_t)(bm + row) * K + k0 + h * 8];
            unsigned* dst = &As[prec][row * 9 + h * 4];
            dst[0] = v.x; dst[1] = v.y; dst[2] = v.z; dst[3] = v.w;
        }
        {
            int it = tid;
            int h = it & 1;
            int row = (it >> 1) & 63;
            int prec = it >> 7;
            const __nv_bfloat16* Bp = prec ? BlT : BhT;
            uint4 v = *(const uint4*)&Bp[(size_t)(bn + row) * K + k0 + h * 8];
            unsigned* dst = &Bs[prec][row * 9 + h * 4];
            dst[0] = v.x; dst[1] = v.y; dst[2] = v.z; dst[3] = v.w;
        }
        __syncthreads();

        unsigned afh[2][4], afl[2][4], bfh[4][2], bfl[4][2];
        #pragma unroll
        for (int mt = 0; mt < 2; mt++) {
            int mb = wm + mt * 16;
            afh[mt][0] = As[0][(mb + g) * 9 + t4];
            afh[mt][1] = As[0][(mb + g + 8) * 9 + t4];
            afh[mt][2] = As[0][(mb + g) * 9 + 4 + t4];
            afh[mt][3] = As[0][(mb + g + 8) * 9 + 4 + t4];
            afl[mt][0] = As[1][(mb + g) * 9 + t4];
            afl[mt][1] = As[1][(mb + g + 8) * 9 + t4];
            afl[mt][2] = As[1][(mb + g) * 9 + 4 + t4];
            afl[mt][3] = As[1][(mb + g + 8) * 9 + 4 + t4];
        }
        #pragma unroll
        for (int nt = 0; nt < 4; nt++) {
            int nb = wn + nt * 8;
            bfh[nt][0] = Bs[0][(nb + g) * 9 + t4];
            bfh[nt][1] = Bs[0][(nb + g) * 9 + 4 + t4];
            bfl[nt][0] = Bs[1][(nb + g) * 9 + t4];
            bfl[nt][1] = Bs[1][(nb + g) * 9 + 4 + t4];
        }
        #pragma unroll
        for (int mt = 0; mt < 2; mt++)
            #pragma unroll
            for (int nt = 0; nt < 4; nt++) {
                MMA_BF16(acc[mt][nt], afh[mt], bfh[nt]);
                MMA_BF16(acc[mt][nt], afh[mt], bfl[nt]);
                MMA_BF16(acc[mt][nt], afl[mt], bfh[nt]);
            }
        __syncthreads();
    }

    #pragma unroll
    for (int mt = 0; mt < 2; mt++) {
        #pragma unroll
        for (int nt = 0; nt < 4; nt++) {
            int row0 = bm + wm + mt * 16 + g;
            int col  = bn + wn + nt * 8 + t4 * 2;
            float b0 = bias[col], b1 = bias[col + 1];
            float r00 = acc[mt][nt][0] + b0; r00 = r00 > 0.f ? r00 : 0.f;
            float r01 = acc[mt][nt][1] + b1; r01 = r01 > 0.f ? r01 : 0.f;
            float r10 = acc[mt][nt][2] + b0; r10 = r10 > 0.f ? r10 : 0.f;
            float r11 = acc[mt][nt][3] + b1; r11 = r11 > 0.f ? r11 : 0.f;
            if (C) {
                *(float2*)&C[(size_t)row0 * N + col]       = make_float2(r00, r01);
                *(float2*)&C[(size_t)(row0 + 8) * N + col] = make_float2(r10, r11);
            }
            if (Ch) {
                unsigned h0 = pack_bf16x2(r00, r01);
                unsigned h1 = pack_bf16x2(r10, r11);
                *(unsigned*)&Ch[(size_t)row0 * N + col]       = h0;
                *(unsigned*)&Ch[(size_t)(row0 + 8) * N + col] = h1;
                *(unsigned*)&Cl[(size_t)row0 * N + col]       = pack_bf16x2_res(r00, r01, h0);
                *(unsigned*)&Cl[(size_t)(row0 + 8) * N + col] = pack_bf16x2_res(r10, r11, h1);
            }
        }
    }
}

// ---------------- PDHG via dense MMA (R12 + split dir1 accumulator chains) ----------------
__global__ __launch_bounds__(256, 1) void pdhg_mma_kernel(
    const float* __restrict__ Zg, const float* __restrict__ Xg,
    float* __restrict__ out)
{
    extern __shared__ __align__(16) char dyn[];
    unsigned* Sb_u  = (unsigned*)(dyn + OFF_SB);    // [64][260]
    unsigned* STb_u = (unsigned*)(dyn + OFF_STB);   // [512][36]
    unsigned* xbh_u = (unsigned*)(dyn + OFF_XBH);   // [16][260]
    unsigned* xbl_u = (unsigned*)(dyn + OFF_XBL);
    unsigned* y1h_u = (unsigned*)(dyn + OFF_Y1H);   // [16][36]
    unsigned* y1l_u = (unsigned*)(dyn + OFF_Y1L);
    float*    part  = (float*)(dyn + OFF_PART);     // [8][16]

    const int tid = threadIdx.x;
    const int w = tid >> 5, lane = tid & 31;
    const int g = lane >> 2, t4 = lane & 3;
    const int row0 = blockIdx.x * 16;
    const float tau = g_tau, sigma = tau;

    {
        const uint4* src = (const uint4*)g_Sb;
        uint4* dst = (uint4*)Sb_u;
        for (int p = tid; p < (64 * 520 * 2) / 16; p += 256) dst[p] = src[p];
        const uint4* src2 = (const uint4*)g_STb;
        uint4* dst2 = (uint4*)STb_u;
        for (int p = tid; p < (512 * 72 * 2) / 16; p += 256) dst2[p] = src2[p];
    }
    for (int p = tid; p < 16 * 260; p += 256) { xbh_u[p] = 0u; xbl_u[p] = 0u; }

    float x[32], y2[32], Zr[32];
    #pragma unroll
    for (int tt = 0; tt < 8; tt++) {
        int col = w * 8 + tt * 64 + 2 * t4;
        float2 z0 = *(const float2*)&Zg[(size_t)(row0 + g) * N_STRUCTS + col];
        float2 z1 = *(const float2*)&Zg[(size_t)(row0 + g + 8) * N_STRUCTS + col];
        Zr[tt * 4 + 0] = z0.x; Zr[tt * 4 + 1] = z0.y;
        Zr[tt * 4 + 2] = z1.x; Zr[tt * 4 + 3] = z1.y;
        #pragma unroll
        for (int e = 0; e < 4; e++) { x[tt * 4 + e] = 0.f; y2[tt * 4 + e] = 0.f; }
    }
    float y1v[4] = {0.f, 0.f, 0.f, 0.f};
    float Bc[4];
    Bc[0] = Xg[(row0 + g) * N_COMBOS + w * 8 + 2 * t4];
    Bc[1] = Xg[(row0 + g) * N_COMBOS + w * 8 + 2 * t4 + 1];
    Bc[2] = Xg[(row0 + g + 8) * N_COMBOS + w * 8 + 2 * t4];
    Bc[3] = Xg[(row0 + g + 8) * N_COMBOS + w * 8 + 2 * t4 + 1];
    __syncthreads();

    for (int it = 0; it < NITERS; it++) {
        // ---- dir1: t = xbar @ S^T ; 4 independent accumulator chains ----
        float c1a[4] = {0.f, 0.f, 0.f, 0.f};
        float c1b[4] = {0.f, 0.f, 0.f, 0.f};
        float c1c[4] = {0.f, 0.f, 0.f, 0.f};
        float c1d[4] = {0.f, 0.f, 0.f, 0.f};
        #pragma unroll 4
        for (int ks = 0; ks < 32; ks += 2) {
            int kw0 = ks * 8, kw1 = (ks + 1) * 8;
            {
                int a0 = g * SB_W + kw0 + t4, a1 = (g + 8) * SB_W + kw0 + t4;
                unsigned ah[4], al[4], bs[2];
                ah[0] = xbh_u[a0]; ah[1] = xbh_u[a1]; ah[2] = xbh_u[a0 + 4]; ah[3] = xbh_u[a1 + 4];
                al[0] = xbl_u[a0]; al[1] = xbl_u[a1]; al[2] = xbl_u[a0 + 4]; al[3] = xbl_u[a1 + 4];
                int br = (w * 8 + g) * SB_W + kw0 + t4;
                bs[0] = Sb_u[br]; bs[1] = Sb_u[br + 4];
                MMA_BF16(c1a, ah, bs);
                MMA_BF16(c1b, al, bs);
            }
            {
                int a0 = g * SB_W + kw1 + t4, a1 = (g + 8) * SB_W + kw1 + t4;
                unsigned ah[4], al[4], bs[2];
                ah[0] = xbh_u[a0]; ah[1] = xbh_u[a1]; ah[2] = xbh_u[a0 + 4]; ah[3] = xbh_u[a1 + 4];
                al[0] = xbl_u[a0]; al[1] = xbl_u[a1]; al[2] = xbl_u[a0 + 4]; al[3] = xbl_u[a1 + 4];
                int br = (w * 8 + g) * SB_W + kw1 + t4;
                bs[0] = Sb_u[br]; bs[1] = Sb_u[br + 4];
                MMA_BF16(c1c, ah, bs);
                MMA_BF16(c1d, al, bs);
            }
        }
        // y1 update, write hi/lo to shared
        #pragma unroll
        for (int e = 0; e < 4; e++) {
            float t1 = (c1a[e] + c1b[e]) + (c1c[e] + c1d[e]);
            y1v[e] = fmaxf(fmaf(sigma, t1 - Bc[e], y1v[e]), 0.f);
        }
        {
            int w0 = g * STB_W + w * 4 + t4;
            int w1 = (g + 8) * STB_W + w * 4 + t4;
            unsigned h0 = pack_bf16x2(y1v[0], y1v[1]);
            unsigned h1 = pack_bf16x2(y1v[2], y1v[3]);
            y1h_u[w0] = h0;
            y1h_u[w1] = h1;
            y1l_u[w0] = pack_bf16x2_res(y1v[0], y1v[1], h0);
            y1l_u[w1] = pack_bf16x2_res(y1v[2], y1v[3], h1);
        }
        __syncthreads();

        // ---- dir2: g = y1 @ S ; 8 independent tt chains ----
        float c2a[8][4];
        #pragma unroll
        for (int tt = 0; tt < 8; tt++)
            #pragma unroll
            for (int e = 0; e < 4; e++) c2a[tt][e] = 0.f;
        #pragma unroll
        for (int ks = 0; ks < 4; ks++) {
            int kw = ks * 8;
            int a0 = g * STB_W + kw + t4, a1 = (g + 8) * STB_W + kw + t4;
            unsigned ah[4], al[4];
            ah[0] = y1h_u[a0]; ah[1] = y1h_u[a1]; ah[2] = y1h_u[a0 + 4]; ah[3] = y1h_u[a1 + 4];
            al[0] = y1l_u[a0]; al[1] = y1l_u[a1]; al[2] = y1l_u[a0 + 4]; al[3] = y1l_u[a1 + 4];
            #pragma unroll
            for (int tt = 0; tt < 8; tt++) {
                int br = (w * 8 + tt * 64 + g) * STB_W + kw + t4;
                unsigned bs[2] = { STb_u[br], STb_u[br + 4] };
                MMA_BF16(c2a[tt], ah, bs);
                MMA_BF16(c2a[tt], al, bs);
            }
        }

        // ---- elementwise: d, per-batch sumsq ----
        float sq0 = 0.f, sq1 = 0.f;
        #pragma unroll
        for (int tt = 0; tt < 8; tt++) {
            #pragma unroll
            for (int e = 0; e < 4; e++) {
                int idx = tt * 4 + e;
                float gv = c2a[tt][e] - y2[idx];
                float v  = fmaf(-tau, gv, x[idx]);
                float d  = v + tau - Zr[idx];
                c2a[tt][e] = d;
                if (e < 2) sq0 = fmaf(d, d, sq0); else sq1 = fmaf(d, d, sq1);
            }
        }
        sq0 += __shfl_xor_sync(0xffffffffu, sq0, 1);
        sq0 += __shfl_xor_sync(0xffffffffu, sq0, 2);
        sq1 += __shfl_xor_sync(0xffffffffu, sq1, 1);
        sq1 += __shfl_xor_sync(0xffffffffu, sq1, 2);
        if (t4 == 0) { part[w * 16 + g] = sq0; part[w * 16 + g + 8] = sq1; }
        __syncthreads();

        float tot0 = 0.f, tot1 = 0.f;
        #pragma unroll
        for (int ww = 0; ww < 8; ww++) {
            tot0 += part[ww * 16 + g];
            tot1 += part[ww * 16 + g + 8];
        }
        float sc0 = fmaxf(1.f - tau / fmaxf(sqrtf(tot0), 1e-12f), 0.f);
        float sc1 = fmaxf(1.f - tau / fmaxf(sqrtf(tot1), 1e-12f), 0.f);

        // ---- prox, xbar, pre-applied y2 update, store xbar hi/lo ----
        #pragma unroll
        for (int tt = 0; tt < 8; tt++) {
            float xb0, xb1, xb2, xb3;
            {
                int i0 = tt * 4 + 0, i1 = tt * 4 + 1;
                float xn0 = fmaf(sc0, c2a[tt][0], Zr[i0]);
                float xn1 = fmaf(sc0, c2a[tt][1], Zr[i1]);
                xb0 = 2.f * xn0 - x[i0]; xb1 = 2.f * xn1 - x[i1];
                x[i0] = xn0; x[i1] = xn1;
                y2[i0] = fmaxf(fmaf(-sigma, xb0, y2[i0]), 0.f);
                y2[i1] = fmaxf(fmaf(-sigma, xb1, y2[i1]), 0.f);
            }
            {
                int i2 = tt * 4 + 2, i3 = tt * 4 + 3;
                float xn2 = fmaf(sc1, c2a[tt][2], Zr[i2]);
                float xn3 = fmaf(sc1, c2a[tt][3], Zr[i3]);
                xb2 = 2.f * xn2 - x[i2]; xb3 = 2.f * xn3 - x[i3];
                x[i2] = xn2; x[i3] = xn3;
                y2[i2] = fmaxf(fmaf(-sigma, xb2, y2[i2]), 0.f);
                y2[i3] = fmaxf(fmaf(-sigma, xb3, y2[i3]), 0.f);
            }
            int w0 = g * SB_W + tt * 32 + w * 4 + t4;
            int w1 = (g + 8) * SB_W + tt * 32 + w * 4 + t4;
            unsigned h0 = pack_bf16x2(xb0, xb1);
            unsigned h1 = pack_bf16x2(xb2, xb3);
            xbh_u[w0] = h0;
            xbh_u[w1] = h1;
            xbl_u[w0] = pack_bf16x2_res(xb0, xb1, h0);
            xbl_u[w1] = pack_bf16x2_res(xb2, xb3, h1);
        }
        __syncthreads();
    }

    #pragma unroll
    for (int tt = 0; tt < 8; tt++) {
        int col = w * 8 + tt * 64 + 2 * t4;
        *(float2*)&out[(size_t)(row0 + g) * N_STRUCTS + col] =
            make_float2(x[tt * 4 + 0], x[tt * 4 + 1]);
        *(float2*)&out[(size_t)(row0 + g + 8) * N_STRUCTS + col] =
            make_float2(x[tt * 4 + 2], x[tt * 4 + 3]);
    }
}

// ---------------- launch ----------------
extern "C" void kernel_launch(void* const* d_in, const int* in_sizes, int n_in,
                              void* d_out, int out_size) {
    const float* X  = (const float*)d_in[0];
    const float* W1 = (const float*)d_in[1];
    const float* b1 = (const float*)d_in[2];
    const float* W2 = (const float*)d_in[3];
    const float* b2 = (const float*)d_in[4];
    const float* W3 = (const float*)d_in[5];
    const float* b3 = (const float*)d_in[6];
    const float* S  = (const float*)d_in[7];
    float* out = (float*)d_out;

    float *Z;
    __nv_bfloat16 *Xh, *Xl, *A1h, *A1l, *A2h, *A2l;
    __nv_bfloat16 *W1hT, *W1lT, *W2hT, *W2lT, *W3hT, *W3lT;
    cudaGetSymbolAddress((void**)&Z,    g_Z);
    cudaGetSymbolAddress((void**)&Xh,   g_Xh);
    cudaGetSymbolAddress((void**)&Xl,   g_Xl);
    cudaGetSymbolAddress((void**)&A1h,  g_A1h);
    cudaGetSymbolAddress((void**)&A1l,  g_A1l);
    cudaGetSymbolAddress((void**)&A2h,  g_A2h);
    cudaGetSymbolAddress((void**)&A2l,  g_A2l);
    cudaGetSymbolAddress((void**)&W1hT, g_W1hT);
    cudaGetSymbolAddress((void**)&W1lT, g_W1lT);
    cudaGetSymbolAddress((void**)&W2hT, g_W2hT);
    cudaGetSymbolAddress((void**)&W2lT, g_W2lT);
    cudaGetSymbolAddress((void**)&W3hT, g_W3hT);
    cudaGetSymbolAddress((void**)&W3lT, g_W3lT);

    static int smem_set = 0;
    if (!smem_set) {
        cudaFuncSetAttribute(pdhg_mma_kernel,
                             cudaFuncAttributeMaxDynamicSharedMemorySize, DYN_PDHG);
        smem_set = 1;
    }

    prep_kernel<<<1, 512>>>(S);
    power_kernel<<<1, 512>>>();
    build_Sbf16<<<(512 * 72 + 511) / 512, 512>>>(S);

    split_matrix<<<(BATCH * N_COMBOS + 255) / 256, 256>>>(X, Xh, Xl, BATCH * N_COMBOS);
    split_transpose<<<(N_COMBOS * HID + 255) / 256, 256>>>(W1, W1hT, W1lT, N_COMBOS, HID);
    split_transpose<<<(HID * HID + 255) / 256, 256>>>(W2, W2hT, W2lT, HID, HID);
    split_transpose<<<(HID * N_STRUCTS + 255) / 256, 256>>>(W3, W3hT, W3lT, HID, N_STRUCTS);

    gemm_bf16split<<<dim3(HID / 64, BATCH / 128), 256>>>(
        Xh, Xl, W1hT, W1lT, b1, nullptr, A1h, A1l, HID, N_COMBOS);
    gemm_bf16split<<<dim3(HID / 64, BATCH / 128), 256>>>(
        A1h, A1l, W2hT, W2lT, b2, nullptr, A2h, A2l, HID, HID);
    gemm_bf16split<<<dim3(N_STRUCTS / 64, BATCH / 128), 256>>>(
        A2h, A2l, W3hT, W3lT, b3, Z, nullptr, nullptr, N_STRUCTS, HID);

    pdhg_mma_kernel<<<BATCH / 16, 256, DYN_PDHG>>>(Z, X, out);
}

// round 16
// speedup vs baseline: 1.5516x; 1.0071x over previous
#include <cuda_runtime.h>
#include <cuda_bf16.h>
#include <math.h>

#define N_COMBOS   64
#define N_STRUCTS  512
#define HID        1024
#define BATCH      2048
#define NITERS     60
#define POW_ITERS  30
#define MAX_NNZ_G  32768

// ---- PDHG-MMA shared layout (bytes) ----
#define SB_W    260          // S row stride in u32 words (520 bf16)
#define STB_W   36           // S^T row stride in u32 words (72 bf16)
#define OFF_SB   0                          // 64*520*2   = 66560
#define OFF_STB  66560                      // 512*72*2   = 73728
#define OFF_XBH  140288                     // 16*520*2   = 16640
#define OFF_XBL  156928                     // 16640
#define OFF_Y1H  173568                     // 16*72*2    = 2304
#define OFF_Y1L  175872                     // 2304
#define OFF_PART 178176                     // 8*16*4     = 512
#define DYN_PDHG 178688

// ---------------- device scratch ----------------
__device__ float g_Z [BATCH * N_STRUCTS];
__device__ float g_tau;

__device__ __nv_bfloat16 g_Xh[BATCH * N_COMBOS];
__device__ __nv_bfloat16 g_Xl[BATCH * N_COMBOS];
__device__ __nv_bfloat16 g_A1h[BATCH * HID];
__device__ __nv_bfloat16 g_A1l[BATCH * HID];
__device__ __nv_bfloat16 g_A2h[BATCH * HID];
__device__ __nv_bfloat16 g_A2l[BATCH * HID];
__device__ __nv_bfloat16 g_W1hT[HID * N_COMBOS];
__device__ __nv_bfloat16 g_W1lT[HID * N_COMBOS];
__device__ __nv_bfloat16 g_W2hT[HID * HID];
__device__ __nv_bfloat16 g_W2lT[HID * HID];
__device__ __nv_bfloat16 g_W3hT[N_STRUCTS * HID];
__device__ __nv_bfloat16 g_W3lT[N_STRUCTS * HID];

__device__ __nv_bfloat16 g_Sb [64 * 520];    // S row-major bf16, padded
__device__ __nv_bfloat16 g_STb[512 * 72];    // S^T row-major bf16, padded

__device__ int            g_row_ptr[N_COMBOS + 1];
__device__ unsigned short g_row_idx[MAX_NNZ_G];
__device__ int            g_col_ptr[N_STRUCTS + 1];
__device__ unsigned char  g_col_idx[MAX_NNZ_G];

// ---------------- split kernels ----------------
__global__ void split_matrix(const float* __restrict__ src,
                             __nv_bfloat16* __restrict__ hi,
                             __nv_bfloat16* __restrict__ lo, int n) {
    int i = blockIdx.x * blockDim.x + threadIdx.x;
    if (i < n) {
        float x = src[i];
        __nv_bfloat16 h = __float2bfloat16(x);
        hi[i] = h;
        lo[i] = __float2bfloat16(x - __bfloat162float(h));
    }
}

__global__ void split_transpose(const float* __restrict__ W,
                                __nv_bfloat16* __restrict__ hiT,
                                __nv_bfloat16* __restrict__ loT, int K, int N) {
    int i = blockIdx.x * blockDim.x + threadIdx.x;
    if (i < K * N) {
        int k = i / N, n = i % N;
        float x = W[i];
        __nv_bfloat16 h = __float2bfloat16(x);
        hiT[n * K + k] = h;
        loT[n * K + k] = __float2bfloat16(x - __bfloat162float(h));
    }
}

__global__ void build_Sbf16(const float* __restrict__ S) {
    int i = blockIdx.x * blockDim.x + threadIdx.x;
    if (i < 64 * 520) {
        int r = i / 520, c = i % 520;
        g_Sb[i] = (c < 512) ? __float2bfloat16(S[r * 512 + c]) : __float2bfloat16(0.f);
    }
    if (i < 512 * 72) {
        int r = i / 72, c = i % 72;
        g_STb[i] = (c < 64) ? __float2bfloat16(S[c * 512 + r]) : __float2bfloat16(0.f);
    }
}

// ---------------- prep: CSR + CSC (for power iteration) ----------------
__global__ __launch_bounds__(512) void prep_kernel(const float* __restrict__ S) {
    __shared__ int cnt[N_STRUCTS];
    int tid = threadIdx.x;

    if (tid < N_COMBOS) {
        int c = 0;
        for (int j = 0; j < N_STRUCTS; j++) if (S[tid * N_STRUCTS + j] != 0.f) c++;
        cnt[tid] = c;
    }
    __syncthreads();
    if (tid == 0) {
        int acc = 0;
        for (int i = 0; i < N_COMBOS; i++) { g_row_ptr[i] = acc; acc += cnt[i]; }
        g_row_ptr[N_COMBOS] = acc;
    }
    __syncthreads();
    if (tid < N_COMBOS) {
        int p = g_row_ptr[tid];
        for (int j = 0; j < N_STRUCTS; j++)
            if (S[tid * N_STRUCTS + j] != 0.f) g_row_idx[p++] = (unsigned short)j;
    }
    __syncthreads();

    {
        int c = 0;
        for (int i = 0; i < N_COMBOS; i++) if (S[i * N_STRUCTS + tid] != 0.f) c++;
        cnt[tid] = c;
    }
    __syncthreads();
    if (tid == 0) {
        int acc = 0;
        for (int j = 0; j < N_STRUCTS; j++) { g_col_ptr[j] = acc; acc += cnt[j]; }
        g_col_ptr[N_STRUCTS] = acc;
    }
    __syncthreads();
    {
        int p = g_col_ptr[tid];
        for (int i = 0; i < N_COMBOS; i++)
            if (S[i * N_STRUCTS + tid] != 0.f) g_col_idx[p++] = (unsigned char)i;
    }
}

// ---------------- power iteration ----------------
__global__ __launch_bounds__(512) void power_kernel() {
    __shared__ float v[N_STRUCTS];
    __shared__ float t[N_COMBOS];
    __shared__ float red[16];
    int tid = threadIdx.x;

    v[tid] = 1.0f / sqrtf((float)N_STRUCTS);
    __syncthreads();

    for (int it = 0; it < POW_ITERS; it++) {
        if (tid < N_COMBOS) {
            float s = 0.f;
            int pe = g_row_ptr[tid + 1];
            for (int p = g_row_ptr[tid]; p < pe; p++) s += v[g_row_idx[p]];
            t[tid] = s;
        }
        __syncthreads();
        float w;
        {
            float s = 0.f;
            int pe = g_col_ptr[tid + 1];
            for (int p = g_col_ptr[tid]; p < pe; p++) s += t[g_col_idx[p]];
            w = s + v[tid];
        }
        float sq = w * w;
        #pragma unroll
        for (int o = 16; o; o >>= 1) sq += __shfl_xor_sync(0xffffffffu, sq, o);
        if ((tid & 31) == 0) red[tid >> 5] = sq;
        __syncthreads();
        float tot = 0.f;
        #pragma unroll
        for (int k = 0; k < 16; k++) tot += red[k];
        v[tid] = w / sqrtf(tot);
        __syncthreads();
    }

    if (tid < N_COMBOS) {
        float s = 0.f;
        int pe = g_row_ptr[tid + 1];
        for (int p = g_row_ptr[tid]; p < pe; p++) s += v[g_row_idx[p]];
        t[tid] = s;
    }
    __syncthreads();
    float w;
    {
        float s = 0.f;
        int pe = g_col_ptr[tid + 1];
        for (int p = g_col_ptr[tid]; p < pe; p++) s += t[g_col_idx[p]];
        w = s + v[tid];
    }
    float dq = v[tid] * w;
    #pragma unroll
    for (int o = 16; o; o >>= 1) dq += __shfl_xor_sync(0xffffffffu, dq, o);
    if ((tid & 31) == 0) red[tid >> 5] = dq;
    __syncthreads();
    if (tid == 0) {
        float tot = 0.f;
        #pragma unroll
        for (int k = 0; k < 16; k++) tot += red[k];
        g_tau = 0.9f / sqrtf(tot);
    }
}

// ---------------- MMA / LDSM macros ----------------
#define MMA_BF16(c, a, b) asm volatile( \
    "mma.sync.aligned.m16n8k16.row.col.f32.bf16.bf16.f32 " \
    "{%0,%1,%2,%3}, {%4,%5,%6,%7}, {%8,%9}, {%0,%1,%2,%3};" \
    : "+f"(c[0]), "+f"(c[1]), "+f"(c[2]), "+f"(c[3]) \
    : "r"(a[0]), "r"(a[1]), "r"(a[2]), "r"(a[3]), "r"(b[0]), "r"(b[1]))

#define LDSM_X4(r, addr) asm volatile( \
    "ldmatrix.sync.aligned.m8n8.x4.shared.b16 {%0,%1,%2,%3}, [%4];" \
    : "=r"((r)[0]), "=r"((r)[1]), "=r"((r)[2]), "=r"((r)[3]) : "r"(addr))

#define LDSM_X2(r, addr) asm volatile( \
    "ldmatrix.sync.aligned.m8n8.x2.shared.b16 {%0,%1}, [%2];" \
    : "=r"((r)[0]), "=r"((r)[1]) : "r"(addr))

__device__ __forceinline__ unsigned smem_u32(const void* p) {
    return (unsigned)__cvta_generic_to_shared(p);
}

__device__ __forceinline__ unsigned pack_bf16x2(float v0, float v1) {
    __nv_bfloat162 b2;
    b2.x = __float2bfloat16(v0);
    b2.y = __float2bfloat16(v1);
    return *(unsigned*)&b2;
}
__device__ __forceinline__ unsigned pack_bf16x2_res(float v0, float v1, unsigned hibits) {
    __nv_bfloat162 hb = *(__nv_bfloat162*)&hibits;
    __nv_bfloat162 b2;
    b2.x = __float2bfloat16(v0 - __bfloat162float(hb.x));
    b2.y = __float2bfloat16(v1 - __bfloat162float(hb.y));
    return *(unsigned*)&b2;
}

// ---------------- bf16-split tensor-core GEMM (R11/R12 verbatim) ----------------
__global__ __launch_bounds__(256) void gemm_bf16split(
    const __nv_bfloat16* __restrict__ Ah, const __nv_bfloat16* __restrict__ Al,
    const __nv_bfloat16* __restrict__ BhT, const __nv_bfloat16* __restrict__ BlT,
    const float* __restrict__ bias,
    float* __restrict__ C,
    __nv_bfloat16* __restrict__ Ch, __nv_bfloat16* __restrict__ Cl,
    int N, int K)
{
    __shared__ __align__(16) unsigned As[2][128 * 9];
    __shared__ __align__(16) unsigned Bs[2][64 * 9];

    const int tid  = threadIdx.x;
    const int bm   = blockIdx.y * 128;
    const int bn   = blockIdx.x * 64;
    const int wid  = tid >> 5, lane = tid & 31;
    const int wm   = (wid & 3) * 32;
    const int wn   = (wid >> 2) * 32;
    const int g    = lane >> 2;
    const int t4   = lane & 3;

    float acc[2][4][4];
    #pragma unroll
    for (int mt = 0; mt < 2; mt++)
        #pragma unroll
        for (int nt = 0; nt < 4; nt++)
            #pragma unroll
            for (int c = 0; c < 4; c++) acc[mt][nt][c] = 0.f;

    const int ksteps = K >> 4;
    for (int ks = 0; ks < ksteps; ks++) {
        const int k0 = ks << 4;
        #pragma unroll
        for (int rep = 0; rep < 2; rep++) {
            int it = tid + rep * 256;
            int h = it & 1;
            int row = (it >> 1) & 127;
            int prec = it >> 8;
            const __nv_bfloat16* Ap = prec ? Al : Ah;
            uint4 v = *(const uint4*)&Ap[(size_t)(bm + row) * K + k0 + h * 8];
            unsigned* dst = &As[prec][row * 9 + h * 4];
            dst[0] = v.x; dst[1] = v.y; dst[2] = v.z; dst[3] = v.w;
        }
        {
            int it = tid;
            int h = it & 1;
            int row = (it >> 1) & 63;
            int prec = it >> 7;
            const __nv_bfloat16* Bp = prec ? BlT : BhT;
            uint4 v = *(const uint4*)&Bp[(size_t)(bn + row) * K + k0 + h * 8];
            unsigned* dst = &Bs[prec][row * 9 + h * 4];
            dst[0] = v.x; dst[1] = v.y; dst[2] = v.z; dst[3] = v.w;
        }
        __syncthreads();

        unsigned afh[2][4], afl[2][4], bfh[4][2], bfl[4][2];
        #pragma unroll
        for (int mt = 0; mt < 2; mt++) {
            int mb = wm + mt * 16;
            afh[mt][0] = As[0][(mb + g) * 9 + t4];
            afh[mt][1] = As[0][(mb + g + 8) * 9 + t4];
            afh[mt][2] = As[0][(mb + g) * 9 + 4 + t4];
            afh[mt][3] = As[0][(mb + g + 8) * 9 + 4 + t4];
            afl[mt][0] = As[1][(mb + g) * 9 + t4];
            afl[mt][1] = As[1][(mb + g + 8) * 9 + t4];
            afl[mt][2] = As[1][(mb + g) * 9 + 4 + t4];
            afl[mt][3] = As[1][(mb + g + 8) * 9 + 4 + t4];
        }
        #pragma unroll
        for (int nt = 0; nt < 4; nt++) {
            int nb = wn + nt * 8;
            bfh[nt][0] = Bs[0][(nb + g) * 9 + t4];
            bfh[nt][1] = Bs[0][(nb + g) * 9 + 4 + t4];
            bfl[nt][0] = Bs[1][(nb + g) * 9 + t4];
            bfl[nt][1] = Bs[1][(nb + g) * 9 + 4 + t4];
        }
        #pragma unroll
        for (int mt = 0; mt < 2; mt++)
            #pragma unroll
            for (int nt = 0; nt < 4; nt++) {
                MMA_BF16(acc[mt][nt], afh[mt], bfh[nt]);
                MMA_BF16(acc[mt][nt], afh[mt], bfl[nt]);
                MMA_BF16(acc[mt][nt], afl[mt], bfh[nt]);
            }
        __syncthreads();
    }

    #pragma unroll
    for (int mt = 0; mt < 2; mt++) {
        #pragma unroll
        for (int nt = 0; nt < 4; nt++) {
            int row0 = bm + wm + mt * 16 + g;
            int col  = bn + wn + nt * 8 + t4 * 2;
            float b0 = bias[col], b1 = bias[col + 1];
            float r00 = acc[mt][nt][0] + b0; r00 = r00 > 0.f ? r00 : 0.f;
            float r01 = acc[mt][nt][1] + b1; r01 = r01 > 0.f ? r01 : 0.f;
            float r10 = acc[mt][nt][2] + b0; r10 = r10 > 0.f ? r10 : 0.f;
            float r11 = acc[mt][nt][3] + b1; r11 = r11 > 0.f ? r11 : 0.f;
            if (C) {
                *(float2*)&C[(size_t)row0 * N + col]       = make_float2(r00, r01);
                *(float2*)&C[(size_t)(row0 + 8) * N + col] = make_float2(r10, r11);
            }
            if (Ch) {
                unsigned h0 = pack_bf16x2(r00, r01);
                unsigned h1 = pack_bf16x2(r10, r11);
                *(unsigned*)&Ch[(size_t)row0 * N + col]       = h0;
                *(unsigned*)&Ch[(size_t)(row0 + 8) * N + col] = h1;
                *(unsigned*)&Cl[(size_t)row0 * N + col]       = pack_bf16x2_res(r00, r01, h0);
                *(unsigned*)&Cl[(size_t)(row0 + 8) * N + col] = pack_bf16x2_res(r10, r11, h1);
            }
        }
    }
}

// ---------------- PDHG via dense MMA (R15 + ldmatrix fragment loads) ----------------
__global__ __launch_bounds__(256, 1) void pdhg_mma_kernel(
    const float* __restrict__ Zg, const float* __restrict__ Xg,
    float* __restrict__ out)
{
    extern __shared__ __align__(16) char dyn[];
    unsigned* Sb_u  = (unsigned*)(dyn + OFF_SB);    // [64][260]
    unsigned* STb_u = (unsigned*)(dyn + OFF_STB);   // [512][36]
    unsigned* xbh_u = (unsigned*)(dyn + OFF_XBH);   // [16][260]
    unsigned* xbl_u = (unsigned*)(dyn + OFF_XBL);
    unsigned* y1h_u = (unsigned*)(dyn + OFF_Y1H);   // [16][36]
    unsigned* y1l_u = (unsigned*)(dyn + OFF_Y1L);
    float*    part  = (float*)(dyn + OFF_PART);     // [8][16]

    const int tid = threadIdx.x;
    const int w = tid >> 5, lane = tid & 31;
    const int g = lane >> 2, t4 = lane & 3;
    const int row0 = blockIdx.x * 16;
    const float tau = g_tau, sigma = tau;

    {
        const uint4* src = (const uint4*)g_Sb;
        uint4* dst = (uint4*)Sb_u;
        for (int p = tid; p < (64 * 520 * 2) / 16; p += 256) dst[p] = src[p];
        const uint4* src2 = (const uint4*)g_STb;
        uint4* dst2 = (uint4*)STb_u;
        for (int p = tid; p < (512 * 72 * 2) / 16; p += 256) dst2[p] = src2[p];
    }
    for (int p = tid; p < 16 * 260; p += 256) { xbh_u[p] = 0u; xbl_u[p] = 0u; }

    // ---- per-lane ldmatrix base addresses (loop-invariant) ----
    const int arow = lane & 15;                 // A-frag: mat row
    const int akof = (lane >> 4) * 4;           // A-frag: k-half word offset
    const int brow = lane & 7;                  // B-frag: n row within tile
    const int bkof = ((lane >> 3) & 1) * 4;     // B-frag: k-half word offset
    const unsigned xah_base = smem_u32(xbh_u) + (arow * SB_W + akof) * 4;
    const unsigned xal_base = smem_u32(xbl_u) + (arow * SB_W + akof) * 4;
    const unsigned sb_base  = smem_u32(Sb_u)  + ((w * 8 + brow) * SB_W + bkof) * 4;
    const unsigned yah_base = smem_u32(y1h_u) + (arow * STB_W + akof) * 4;
    const unsigned yal_base = smem_u32(y1l_u) + (arow * STB_W + akof) * 4;
    const unsigned stb_base = smem_u32(STb_u) + ((w * 8 + brow) * STB_W + bkof) * 4;

    float x[32], y2[32], Zr[32];
    #pragma unroll
    for (int tt = 0; tt < 8; tt++) {
        int col = w * 8 + tt * 64 + 2 * t4;
        float2 z0 = *(const float2*)&Zg[(size_t)(row0 + g) * N_STRUCTS + col];
        float2 z1 = *(const float2*)&Zg[(size_t)(row0 + g + 8) * N_STRUCTS + col];
        Zr[tt * 4 + 0] = z0.x; Zr[tt * 4 + 1] = z0.y;
        Zr[tt * 4 + 2] = z1.x; Zr[tt * 4 + 3] = z1.y;
        #pragma unroll
        for (int e = 0; e < 4; e++) { x[tt * 4 + e] = 0.f; y2[tt * 4 + e] = 0.f; }
    }
    float y1v[4] = {0.f, 0.f, 0.f, 0.f};
    float Bc[4];
    Bc[0] = Xg[(row0 + g) * N_COMBOS + w * 8 + 2 * t4];
    Bc[1] = Xg[(row0 + g) * N_COMBOS + w * 8 + 2 * t4 + 1];
    Bc[2] = Xg[(row0 + g + 8) * N_COMBOS + w * 8 + 2 * t4];
    Bc[3] = Xg[(row0 + g + 8) * N_COMBOS + w * 8 + 2 * t4 + 1];
    __syncthreads();

    for (int it = 0; it < NITERS; it++) {
        // ---- dir1: t = xbar @ S^T ; ldmatrix loads, split chains ----
        float c1a[4] = {0.f, 0.f, 0.f, 0.f};
        float c1b[4] = {0.f, 0.f, 0.f, 0.f};
        float c1c[4] = {0.f, 0.f, 0.f, 0.f};
        float c1d[4] = {0.f, 0.f, 0.f, 0.f};
        {
            unsigned ahp = xah_base, alp = xal_base, sbp = sb_base;
            #pragma unroll 4
            for (int ks = 0; ks < 32; ks += 2) {
                unsigned ah0[4], al0[4], bs0[2], ah1[4], al1[4], bs1[2];
                LDSM_X4(ah0, ahp);
                LDSM_X4(al0, alp);
                LDSM_X2(bs0, sbp);
                LDSM_X4(ah1, ahp + 32);
                LDSM_X4(al1, alp + 32);
                LDSM_X2(bs1, sbp + 32);
                ahp += 64; alp += 64; sbp += 64;
                MMA_BF16(c1a, ah0, bs0);
                MMA_BF16(c1b, al0, bs0);
                MMA_BF16(c1c, ah1, bs1);
                MMA_BF16(c1d, al1, bs1);
            }
        }
        // y1 update, write hi/lo to shared
        #pragma unroll
        for (int e = 0; e < 4; e++) {
            float t1 = (c1a[e] + c1b[e]) + (c1c[e] + c1d[e]);
            y1v[e] = fmaxf(fmaf(sigma, t1 - Bc[e], y1v[e]), 0.f);
        }
        {
            int w0 = g * STB_W + w * 4 + t4;
            int w1 = (g + 8) * STB_W + w * 4 + t4;
            unsigned h0 = pack_bf16x2(y1v[0], y1v[1]);
            unsigned h1 = pack_bf16x2(y1v[2], y1v[3]);
            y1h_u[w0] = h0;
            y1h_u[w1] = h1;
            y1l_u[w0] = pack_bf16x2_res(y1v[0], y1v[1], h0);
            y1l_u[w1] = pack_bf16x2_res(y1v[2], y1v[3], h1);
        }
        __syncthreads();

        // ---- dir2: g = y1 @ S ; ldmatrix loads ----
        float c2a[8][4];
        #pragma unroll
        for (int tt = 0; tt < 8; tt++)
            #pragma unroll
            for (int e = 0; e < 4; e++) c2a[tt][e] = 0.f;
        #pragma unroll
        for (int ks = 0; ks < 4; ks++) {
            unsigned ah[4], al[4];
            LDSM_X4(ah, yah_base + ks * 32);
            LDSM_X4(al, yal_base + ks * 32);
            #pragma unroll
            for (int tt = 0; tt < 8; tt++) {
                unsigned bs[2];
                LDSM_X2(bs, stb_base + (unsigned)(tt * 64 * STB_W * 4 + ks * 32));
                MMA_BF16(c2a[tt], ah, bs);
                MMA_BF16(c2a[tt], al, bs);
            }
        }

        // ---- elementwise: d, per-batch sumsq ----
        float sq0 = 0.f, sq1 = 0.f;
        #pragma unroll
        for (int tt = 0; tt < 8; tt++) {
            #pragma unroll
            for (int e = 0; e < 4; e++) {
                int idx = tt * 4 + e;
                float gv = c2a[tt][e] - y2[idx];
                float v  = fmaf(-tau, gv, x[idx]);
                float d  = v + tau - Zr[idx];
                c2a[tt][e] = d;
                if (e < 2) sq0 = fmaf(d, d, sq0); else sq1 = fmaf(d, d, sq1);
            }
        }
        sq0 += __shfl_xor_sync(0xffffffffu, sq0, 1);
        sq0 += __shfl_xor_sync(0xffffffffu, sq0, 2);
        sq1 += __shfl_xor_sync(0xffffffffu, sq1, 1);
        sq1 += __shfl_xor_sync(0xffffffffu, sq1, 2);
        if (t4 == 0) { part[w * 16 + g] = sq0; part[w * 16 + g + 8] = sq1; }
        __syncthreads();

        float tot0 = 0.f, tot1 = 0.f;
        #pragma unroll
        for (int ww = 0; ww < 8; ww++) {
            tot0 += part[ww * 16 + g];
            tot1 += part[ww * 16 + g + 8];
        }
        float sc0 = fmaxf(1.f - tau / fmaxf(sqrtf(tot0), 1e-12f), 0.f);
        float sc1 = fmaxf(1.f - tau / fmaxf(sqrtf(tot1), 1e-12f), 0.f);

        // ---- prox, xbar, pre-applied y2 update, store xbar hi/lo ----
        #pragma unroll
        for (int tt = 0; tt < 8; tt++) {
            float xb0, xb1, xb2, xb3;
            {
                int i0 = tt * 4 + 0, i1 = tt * 4 + 1;
                float xn0 = fmaf(sc0, c2a[tt][0], Zr[i0]);
                float xn1 = fmaf(sc0, c2a[tt][1], Zr[i1]);
                xb0 = 2.f * xn0 - x[i0]; xb1 = 2.f * xn1 - x[i1];
                x[i0] = xn0; x[i1] = xn1;
                y2[i0] = fmaxf(fmaf(-sigma, xb0, y2[i0]), 0.f);
                y2[i1] = fmaxf(fmaf(-sigma, xb1, y2[i1]), 0.f);
            }
            {
                int i2 = tt * 4 + 2, i3 = tt * 4 + 3;
                float xn2 = fmaf(sc1, c2a[tt][2], Zr[i2]);
                float xn3 = fmaf(sc1, c2a[tt][3], Zr[i3]);
                xb2 = 2.f * xn2 - x[i2]; xb3 = 2.f * xn3 - x[i3];
                x[i2] = xn2; x[i3] = xn3;
                y2[i2] = fmaxf(fmaf(-sigma, xb2, y2[i2]), 0.f);
                y2[i3] = fmaxf(fmaf(-sigma, xb3, y2[i3]), 0.f);
            }
            int w0 = g * SB_W + tt * 32 + w * 4 + t4;
            int w1 = (g + 8) * SB_W + tt * 32 + w * 4 + t4;
            unsigned h0 = pack_bf16x2(xb0, xb1);
            unsigned h1 = pack_bf16x2(xb2, xb3);
            xbh_u[w0] = h0;
            xbh_u[w1] = h1;
            xbl_u[w0] = pack_bf16x2_res(xb0, xb1, h0);
            xbl_u[w1] = pack_bf16x2_res(xb2, xb3, h1);
        }
        __syncthreads();
    }

    #pragma unroll
    for (int tt = 0; tt < 8; tt++) {
        int col = w * 8 + tt * 64 + 2 * t4;
        *(float2*)&out[(size_t)(row0 + g) * N_STRUCTS + col] =
            make_float2(x[tt * 4 + 0], x[tt * 4 + 1]);
        *(float2*)&out[(size_t)(row0 + g + 8) * N_STRUCTS + col] =
            make_float2(x[tt * 4 + 2], x[tt * 4 + 3]);
    }
}

// ---------------- launch ----------------
extern "C" void kernel_launch(void* const* d_in, const int* in_sizes, int n_in,
                              void* d_out, int out_size) {
    const float* X  = (const float*)d_in[0];
    const float* W1 = (const float*)d_in[1];
    const float* b1 = (const float*)d_in[2];
    const float* W2 = (const float*)d_in[3];
    const float* b2 = (const float*)d_in[4];
    const float* W3 = (const float*)d_in[5];
    const float* b3 = (const float*)d_in[6];
    const float* S  = (const float*)d_in[7];
    float* out = (float*)d_out;

    float *Z;
    __nv_bfloat16 *Xh, *Xl, *A1h, *A1l, *A2h, *A2l;
    __nv_bfloat16 *W1hT, *W1lT, *W2hT, *W2lT, *W3hT, *W3lT;
    cudaGetSymbolAddress((void**)&Z,    g_Z);
    cudaGetSymbolAddress((void**)&Xh,   g_Xh);
    cudaGetSymbolAddress((void**)&Xl,   g_Xl);
    cudaGetSymbolAddress((void**)&A1h,  g_A1h);
    cudaGetSymbolAddress((void**)&A1l,  g_A1l);
    cudaGetSymbolAddress((void**)&A2h,  g_A2h);
    cudaGetSymbolAddress((void**)&A2l,  g_A2l);
    cudaGetSymbolAddress((void**)&W1hT, g_W1hT);
    cudaGetSymbolAddress((void**)&W1lT, g_W1lT);
    cudaGetSymbolAddress((void**)&W2hT, g_W2hT);
    cudaGetSymbolAddress((void**)&W2lT, g_W2lT);
    cudaGetSymbolAddress((void**)&W3hT, g_W3hT);
    cudaGetSymbolAddress((void**)&W3lT, g_W3lT);

    static int smem_set = 0;
    if (!smem_set) {
        cudaFuncSetAttribute(pdhg_mma_kernel,
                             cudaFuncAttributeMaxDynamicSharedMemorySize, DYN_PDHG);
        smem_set = 1;
    }

    prep_kernel<<<1, 512>>>(S);
    power_kernel<<<1, 512>>>();
    build_Sbf16<<<(512 * 72 + 511) / 512, 512>>>(S);

    split_matrix<<<(BATCH * N_COMBOS + 255) / 256, 256>>>(X, Xh, Xl, BATCH * N_COMBOS);
    split_transpose<<<(N_COMBOS * HID + 255) / 256, 256>>>(W1, W1hT, W1lT, N_COMBOS, HID);
    split_transpose<<<(HID * HID + 255) / 256, 256>>>(W2, W2hT, W2lT, HID, HID);
    split_transpose<<<(HID * N_STRUCTS + 255) / 256, 256>>>(W3, W3hT, W3lT, HID, N_STRUCTS);

    gemm_bf16split<<<dim3(HID / 64, BATCH / 128), 256>>>(
        Xh, Xl, W1hT, W1lT, b1, nullptr, A1h, A1l, HID, N_COMBOS);
    gemm_bf16split<<<dim3(HID / 64, BATCH / 128), 256>>>(
        A1h, A1l, W2hT, W2lT, b2, nullptr, A2h, A2l, HID, HID);
    gemm_bf16split<<<dim3(N_STRUCTS / 64, BATCH / 128), 256>>>(
        A2h, A2l, W3hT, W3lT, b3, Z, nullptr, nullptr, N_STRUCTS, HID);

    pdhg_mma_kernel<<<BATCH / 16, 256, DYN_PDHG>>>(Z, X, out);
}